// round 9
// baseline (speedup 1.0000x reference)
#include <cuda_runtime.h>

// MN neuron scan: T=1000 steps, B*N = 32768 independent neurons.
//
// R8: packed f32x2 arithmetic (Blackwell FFMA2 path).
//  - 4 neurons/thread as 2 packed f32x2 pairs: halves instruction count vs
//    scalar (we are warp-issue-bound: IPC 0.46, pipes <30%), and gives each
//    of the 256 warps its own SMSP with 2 independent dependency chains.
//  - add/mul/fma.rn.f32x2 are per-lane IEEE rn ops -> the validated
//    XLA-uncontracted, bit-exact op ordering is preserved per neuron.
//    Subtraction a-b is computed as add(a, mul(x,-k)) where the negated
//    product is exact (-rn(p) == rn(-p)).
//  - LDG.128/STG.128 per step; ping-pong float4 prefetch, 10-step distance
//    (~1100 cyc > ~1050-cyc NAT DRAM latency).

#define T_STEPS 1000
#define NN      512
#define BN      32768          // B * N
#define NT      (BN / 4)       // threads (4 neurons each) = 8192
#define UPF     5              // steps per prefetch group (ping-pong x2)

typedef unsigned long long u64;

__device__ __forceinline__ u64 pk2(float lo, float hi) {
    u64 r; asm("mov.b64 %0, {%1, %2};" : "=l"(r) : "f"(lo), "f"(hi)); return r;
}
__device__ __forceinline__ void up2(u64 v, float& lo, float& hi) {
    asm("mov.b64 {%0, %1}, %2;" : "=f"(lo), "=f"(hi) : "l"(v));
}
__device__ __forceinline__ u64 add2(u64 a, u64 b) {
    u64 d; asm("add.rn.f32x2 %0, %1, %2;" : "=l"(d) : "l"(a), "l"(b)); return d;
}
__device__ __forceinline__ u64 mul2(u64 a, u64 b) {
    u64 d; asm("mul.rn.f32x2 %0, %1, %2;" : "=l"(d) : "l"(a), "l"(b)); return d;
}
__device__ __forceinline__ u64 fma2(u64 a, u64 b, u64 c) {
    u64 d; asm("fma.rn.f32x2 %0, %1, %2, %3;" : "=l"(d) : "l"(a), "l"(b), "l"(c)); return d;
}

struct PState { u64 V, i1, i2, Th; };
struct PConst {
    u64 nK1, nK2, DT, NEL, nG, NTIN, nB, NEG1, R1, R2;
};

// One bit-exact step for a packed pair of neurons. Returns packed spikes {0,1}.
__device__ __forceinline__ void step_pair(PState& s, u64 xt,
                                          u64 lw, u64 av, u64 A1v, u64 A2v,
                                          const PConst& C,
                                          float& spx, float& spy)
{
    // i1 = i1 - rn(rn(K1*i1)*DT)   (via exact negation)
    u64 m1 = mul2(s.i1, C.nK1); m1 = mul2(m1, C.DT); s.i1 = add2(s.i1, m1);
    u64 m2 = mul2(s.i2, C.nK2); m2 = mul2(m2, C.DT); s.i2 = add2(s.i2, m2);

    // V += DT * (((lin*xt + i1) + i2) - G*(V-EL))
    u64 lx  = mul2(lw, xt);
    u64 ss  = add2(lx, s.i1);
    ss      = add2(ss, s.i2);
    u64 vel = add2(s.V, C.NEL);       // rn(V - EL)
    u64 gqn = mul2(vel, C.nG);        // -rn(G*(V-EL))
    u64 dv  = add2(ss, gqn);          // rn(s - gq)
    dv      = mul2(dv, C.DT);
    s.V     = add2(s.V, dv);

    // Thr += DT * (a*(V-EL) - B*(Thr-TINF))
    u64 ve2 = add2(s.V, C.NEL);
    u64 t1  = mul2(av, ve2);
    u64 tt  = add2(s.Th, C.NTIN);     // rn(Thr - TINF)
    u64 t2n = mul2(tt, C.nB);         // -rn(B*(Thr-TINF))
    u64 dd  = add2(t1, t2n);
    dd      = mul2(dd, C.DT);
    s.Th    = add2(s.Th, dd);

    // vm = V - Thr
    u64 vm  = fma2(s.Th, C.NEG1, s.V);

    // reset candidates (two-rounded, as reference: rn(rn(R*i)+A))
    u64 i1n = add2(mul2(s.i1, C.R1), A1v);
    u64 i2n = add2(mul2(s.i2, C.R2), A2v);

    // per-lane spike + exact selects
    float vmx, vmy;  up2(vm, vmx, vmy);
    const bool px = (vmx > 0.0f);
    const bool py = (vmy > 0.0f);

    float ax, ay, bx, by;

    up2(s.i1, ax, ay); up2(i1n, bx, by);
    s.i1 = pk2(px ? bx : ax, py ? by : ay);

    up2(s.i2, ax, ay); up2(i2n, bx, by);
    s.i2 = pk2(px ? bx : ax, py ? by : ay);

    up2(s.Th, ax, ay);
    s.Th = pk2(px ? fmaxf(ax, -0.06f) : ax, py ? fmaxf(ay, -0.06f) : ay);

    up2(s.V, ax, ay);
    s.V = pk2(px ? -0.07f : ax, py ? -0.07f : ay);

    spx = px ? 1.0f : 0.0f;
    spy = py ? 1.0f : 0.0f;
}

__global__ __launch_bounds__(32)
void mn_neuron_kernel(const float* __restrict__ x,
                      const float* __restrict__ lin,
                      const float* __restrict__ aarr,
                      const float* __restrict__ A1arr,
                      const float* __restrict__ A2arr,
                      float* __restrict__ out)
{
    const int gid = blockIdx.x * 32 + threadIdx.x;   // quad id in [0, NT)
    const int n0  = (4 * gid) & (NN - 1);            // 4-aligned neuron index

    // Packed constants
    PConst C;
    C.nK1  = pk2(-200.0f, -200.0f);
    C.nK2  = pk2(-20.0f, -20.0f);
    C.DT   = pk2(0.01f, 0.01f);
    C.NEL  = pk2(0.07f, 0.07f);      // -EL
    C.nG   = pk2(-45.24007797241211f, -45.24007797241211f);
    C.NTIN = pk2(0.05f, 0.05f);      // -TINF
    C.nB   = pk2(-12.77495288848877f, -12.77495288848877f);
    C.NEG1 = pk2(-1.0f, -1.0f);
    C.R1   = pk2(0.3858567178249359f, 0.3858567178249359f);
    C.R2   = pk2(-1.1421641111373901f, -1.1421641111373901f);

    // Per-quad parameters (16B-aligned)
    const float4 l4  = *(const float4*)(lin   + n0);
    const float4 a4  = *(const float4*)(aarr  + n0);
    const float4 A14 = *(const float4*)(A1arr + n0);
    const float4 A24 = *(const float4*)(A2arr + n0);
    const u64 lwA = pk2(l4.x,  l4.y),  lwB = pk2(l4.z,  l4.w);
    const u64 avA = pk2(a4.x,  a4.y),  avB = pk2(a4.z,  a4.w);
    const u64 A1A = pk2(A14.x, A14.y), A1B = pk2(A14.z, A14.w);
    const u64 A2A = pk2(A24.x, A24.y), A2B = pk2(A24.z, A24.w);

    PState sA = { pk2(-0.07f, -0.07f), pk2(0.f, 0.f), pk2(0.f, 0.f), pk2(-0.05f, -0.05f) };
    PState sB = sA;

    const float4* xp = (const float4*)x   + gid;   // stride NT per step
    float4*       op = (float4*)      out + gid;

    // Prime two prefetch groups (10 LDG.128 in flight, ~10-step distance)
    float4 bufA[UPF], bufB[UPF];
#pragma unroll
    for (int u = 0; u < UPF; ++u) bufA[u] = xp[(size_t)u * NT];
#pragma unroll
    for (int u = 0; u < UPF; ++u) bufB[u] = xp[(size_t)(UPF + u) * NT];

    for (int t0 = 0; t0 < T_STEPS; t0 += 2 * UPF) {
        float4 cur[UPF];

        // ---- phase A ----
#pragma unroll
        for (int u = 0; u < UPF; ++u) cur[u] = bufA[u];
        if (t0 + 2 * UPF < T_STEPS) {
            const float4* np = xp + (size_t)(t0 + 2 * UPF) * NT;
#pragma unroll
            for (int u = 0; u < UPF; ++u) bufA[u] = np[(size_t)u * NT];
        }
#pragma unroll
        for (int u = 0; u < UPF; ++u) {
            const u64 xA = pk2(cur[u].x, cur[u].y);
            const u64 xB = pk2(cur[u].z, cur[u].w);
            float4 sp;
            step_pair(sA, xA, lwA, avA, A1A, A2A, C, sp.x, sp.y);
            step_pair(sB, xB, lwB, avB, A1B, A2B, C, sp.z, sp.w);
            op[(size_t)(t0 + u) * NT] = sp;
        }

        // ---- phase B ----
#pragma unroll
        for (int u = 0; u < UPF; ++u) cur[u] = bufB[u];
        if (t0 + 3 * UPF < T_STEPS) {
            const float4* np = xp + (size_t)(t0 + 3 * UPF) * NT;
#pragma unroll
            for (int u = 0; u < UPF; ++u) bufB[u] = np[(size_t)u * NT];
        }
#pragma unroll
        for (int u = 0; u < UPF; ++u) {
            const u64 xA = pk2(cur[u].x, cur[u].y);
            const u64 xB = pk2(cur[u].z, cur[u].w);
            float4 sp;
            step_pair(sA, xA, lwA, avA, A1A, A2A, C, sp.x, sp.y);
            step_pair(sB, xB, lwB, avB, A1B, A2B, C, sp.z, sp.w);
            op[(size_t)(t0 + UPF + u) * NT] = sp;
        }
    }
}

extern "C" void kernel_launch(void* const* d_in, const int* in_sizes, int n_in,
                              void* d_out, int out_size)
{
    const float* x   = (const float*)d_in[0];  // [T, B, N]
    const float* lin = (const float*)d_in[1];  // [1, N]
    const float* a   = (const float*)d_in[2];  // [1, N]
    const float* A1  = (const float*)d_in[3];  // [1, N]
    const float* A2  = (const float*)d_in[4];  // [1, N]
    float* out = (float*)d_out;                // [T, B, N]

    (void)in_sizes; (void)n_in; (void)out_size;

    mn_neuron_kernel<<<NT / 32, 32>>>(x, lin, a, A1, A2, out);
}